// round 16
// baseline (speedup 1.0000x reference)
#include <cuda.h>
#include <cuda_runtime.h>
#include <cstdint>
#include <cstddef>

// Problem constants
#define BATCH 512
#define SEQ   256
#define XD    512
#define HD    1024
#define KTOT  (HD + XD)   // 1536

// GEMM tiling
#define MT   64
#define NT   64
#define KT   128           // k per stage = 4 chunks of 32 (SW128 128B rows)
#define NCH  4
#define NKT  (KTOT / KT)   // 12 stages per step (0..3 = X, 4..11 = H)
#define NXS  4             // X stages per step
#define THREADS 544        // 16 consumer warps + 1 producer warp
#define NS   3             // mbarrier ring stages
#define CHUNK_BYTES 8192                    // 64 rows x 128B
#define A_BYTES (NCH * CHUNK_BYTES)         // 32768
#define B_BYTES (NCH * CHUNK_BYTES)         // 32768
#define STAGE_BYTES (A_BYTES + B_BYTES)     // 65536
#define SCRATCH_FLOATS (4 * 32 * 36)        // 4608 floats = 18432 B
#define SMEM_BYTES (NS * STAGE_BYTES + SCRATCH_FLOATS * 4 + 1024)  // 216064

// Static device scratch (allocation-free rule)
__device__ float    g_W[HD * KTOT];           // prepacked tf32-rounded [W_hh | W_xh]
__device__ float    g_H[2][BATCH * HD];       // ping-pong hidden state
__device__ unsigned g_step[128];              // per-CTA completed-step flags [y*16+x]

__device__ __forceinline__ float tf32r(float x) {
    uint32_t u;
    asm("cvt.rna.tf32.f32 %0, %1;" : "=r"(u) : "f"(x));
    return __uint_as_float(u);
}

__device__ __forceinline__ uint32_t tf32r_u(uint32_t x) {
    uint32_t u;
    asm("cvt.rna.tf32.f32 %0, %1;" : "=r"(u) : "f"(__uint_as_float(x)));
    return u;
}

__device__ __forceinline__ uint32_t smem_u32(const void* p) {
    return (uint32_t)__cvta_generic_to_shared(p);
}

__device__ __forceinline__ unsigned ldacq(const unsigned* p) {
    unsigned v;
    asm volatile("ld.acquire.gpu.u32 %0, [%1];" : "=r"(v) : "l"(p) : "memory");
    return v;
}
__device__ __forceinline__ void strel(unsigned* p, unsigned v) {
    asm volatile("st.release.gpu.u32 [%0], %1;" :: "l"(p), "r"(v) : "memory");
}

#define MMA_TF32(c, a, b)                                                   \
    asm volatile(                                                           \
        "mma.sync.aligned.m16n8k8.row.col.f32.tf32.tf32.f32 "               \
        "{%0,%1,%2,%3}, {%4,%5,%6,%7}, {%8,%9}, {%0,%1,%2,%3};\n"           \
        : "+f"((c)[0]), "+f"((c)[1]), "+f"((c)[2]), "+f"((c)[3])            \
        : "r"((a)[0]), "r"((a)[1]), "r"((a)[2]), "r"((a)[3]),               \
          "r"((b)[0]), "r"((b)[1]))

#define LDSM_X4(r0, r1, r2, r3, addr)                                       \
    asm volatile("ldmatrix.sync.aligned.m8n8.x4.shared.b16 {%0,%1,%2,%3}, [%4];" \
        : "=r"(r0), "=r"(r1), "=r"(r2), "=r"(r3) : "r"(addr))

#define MBARRIER_INIT(a, c) \
    asm volatile("mbarrier.init.shared.b64 [%0], %1;" :: "r"(a), "r"((uint32_t)(c)) : "memory")
#define MBARRIER_ARRIVE(a) \
    asm volatile("mbarrier.arrive.shared.b64 _, [%0];" :: "r"(a) : "memory")
#define MBARRIER_EXPECT_TX(a, b) \
    asm volatile("mbarrier.arrive.expect_tx.shared.b64 _, [%0], %1;" :: "r"(a), "r"((uint32_t)(b)) : "memory")
#define FENCE_PROXY_ASYNC() \
    asm volatile("fence.proxy.async.shared::cta;" ::: "memory")
#define BAR_CONS() \
    asm volatile("bar.sync 1, 512;" ::: "memory")   // consumers only (512 threads)

#define MBARRIER_WAIT_PARITY(mbar_addr, phase) do {                              \
    uint32_t _m = (mbar_addr), _p = (phase), _d;                                 \
    asm volatile("{\n\t.reg .pred p;\n\t"                                        \
        "mbarrier.try_wait.parity.acquire.cta.shared::cta.b64 p, [%1], %2;\n\t"  \
        "selp.b32 %0, 1, 0, p;\n\t}" : "=r"(_d) : "r"(_m), "r"(_p) : "memory");  \
    if (!_d) {                                                                   \
        asm volatile("{\n\t.reg .pred P1;\n\t"                                   \
            "WL_%=:\n\t"                                                         \
            "mbarrier.try_wait.parity.acquire.cta.shared::cta.b64 P1, [%0], %1, 0x989680;\n\t" \
            "@P1 bra.uni WD_%=;\n\t"                                             \
            "bra.uni WL_%=;\n\t"                                                 \
            "WD_%=:\n\t}" :: "r"(_m), "r"(_p) : "memory");                       \
    }                                                                            \
} while (0)

#define TMA_LOAD_3D(smem_addr, map_ptr, cx, cy, cz, mbar) \
    asm volatile("cp.async.bulk.tensor.3d.shared::cta.global.tile.mbarrier::complete_tx::bytes " \
                 "[%0], [%1, {%2, %3, %4}], [%5];" \
                 :: "r"((uint32_t)(smem_addr)), "l"(map_ptr), \
                    "r"((int)(cx)), "r"((int)(cy)), "r"((int)(cz)), \
                    "r"((uint32_t)(mbar)) : "memory")

// SW128 swizzle: byte offset within a 64x128B tile
__device__ __forceinline__ uint32_t sw(int r, int c) {
    return (uint32_t)(r * 128 + ((c * 4) ^ ((r & 7) * 16)));
}

// ---------------------------------------------------------------------------
// Prep kernels
// ---------------------------------------------------------------------------
__global__ void pack_w_kernel(const float* __restrict__ Whh,
                              const float* __restrict__ Wxh) {
    int idx = blockIdx.x * 256 + threadIdx.x;
    if (idx >= HD * KTOT) return;
    int n = idx / KTOT;
    int k = idx - n * KTOT;
    float v = (k < HD) ? Whh[n * HD + k] : Wxh[n * XD + (k - HD)];
    g_W[idx] = tf32r(v);
}

__global__ void zero_kernel() {
    g_H[0][blockIdx.x * 1024 + threadIdx.x] = 0.0f;
    if (blockIdx.x == 0 && threadIdx.x < 128) g_step[threadIdx.x] = 0u;
}

// ---------------------------------------------------------------------------
// PERSISTENT RNN kernel: all 256 steps in one launch.
// Grid (16, 8) = 128 CTAs (all co-resident). 17 warps:
//   warps 0..15 consumers: (warpM 2) x (warpN 2) x (warpK 4), warp tile 32x32
//   warp 16: free-running TMA producer over 256*12 stages
// Stage order per step: X stages (0..3, ungated; raw X rounded in-register)
// then H stages (4..11), each gated ONLY on its 2 writer CTAs (x=2j, 2j+1 of
// this y-row) via per-CTA release flags -> release pipelines across x.
// ---------------------------------------------------------------------------
__global__ __launch_bounds__(THREADS, 1)
void rnn_kernel(const __grid_constant__ CUtensorMap tH0,
                const __grid_constant__ CUtensorMap tH1,
                const __grid_constant__ CUtensorMap tX,
                const __grid_constant__ CUtensorMap tB_W,
                const float* __restrict__ bias) {
    extern __shared__ __align__(16) float S[];
    __shared__ __align__(8) uint64_t mb_full[NS], mb_empty[NS];

    const int tid   = threadIdx.x;
    const int mBase = blockIdx.y * MT;
    const int nBase = blockIdx.x * NT;
    const int gy    = blockIdx.y;
    const int lane  = tid & 31;
    const int warp  = tid >> 5;          // 0..16
    const int warpK = (warp >> 2) & 3;   // consumers: 0..3
    const int warpM = (warp >> 1) & 1;
    const int warpN = warp & 1;
    const int g     = lane >> 2;         // 0..7
    const int tig   = lane & 3;          // 0..3

    const uint32_t dynBase = (smem_u32(S) + 1023u) & ~1023u;

    if (tid == 0) {
        for (int s = 0; s < NS; s++) {
            MBARRIER_INIT(smem_u32(&mb_full[s]), 1);    // expect_tx producer
            MBARRIER_INIT(smem_u32(&mb_empty[s]), 16);  // one per consumer warp
        }
        FENCE_PROXY_ASYNC();
    }
    __syncthreads();

    if (warp == 16) {
        // ---------------- Producer warp (single thread) ----------------
        if (lane == 0) {
            int s = 0;
            for (int t = 0; t < SEQ; t++) {
                for (int kt = 0; kt < NKT; kt++, s++) {
                    const int slot = s % NS;
                    const int j    = s / NS;
                    if (s >= NS)
                        MBARRIER_WAIT_PARITY(smem_u32(&mb_empty[slot]), (j - 1) & 1);
                    if (kt >= NXS) {
                        // H stage kt needs H cols [(kt-4)*128, +128) -> writers
                        // x = 2(kt-4), 2(kt-4)+1 of this y-row, at >= t steps.
                        const unsigned* f = &g_step[gy * 16 + (kt - NXS) * 2];
                        const unsigned need = (unsigned)t;
                        while (ldacq(&f[0]) < need) {}
                        while (ldacq(&f[1]) < need) {}
                    }
                    const uint32_t aAddr = dynBase + slot * STAGE_BYTES;
                    const uint32_t bAddr = aAddr + A_BYTES;
                    const uint32_t fb = smem_u32(&mb_full[slot]);
                    MBARRIER_EXPECT_TX(fb, STAGE_BYTES);
                    if (kt < NXS) {
                        const int xk = kt * KT;
#pragma unroll
                        for (int ch = 0; ch < NCH; ch++) {
                            TMA_LOAD_3D(aAddr + ch * CHUNK_BYTES, &tX,
                                        xk + ch * 32, t, mBase, fb);
                            TMA_LOAD_3D(bAddr + ch * CHUNK_BYTES, &tB_W,
                                        HD + xk + ch * 32, nBase, 0, fb);
                        }
                    } else {
                        const int hk = (kt - NXS) * KT;
                        const CUtensorMap* th = (t & 1) ? &tH1 : &tH0;
#pragma unroll
                        for (int ch = 0; ch < NCH; ch++) {
                            TMA_LOAD_3D(aAddr + ch * CHUNK_BYTES, th,
                                        hk + ch * 32, mBase, 0, fb);
                            TMA_LOAD_3D(bAddr + ch * CHUNK_BYTES, &tB_W,
                                        hk + ch * 32, nBase, 0, fb);
                        }
                    }
                }
            }
        }
        return;   // producer never touches CTA-wide barriers again
    }

    // ---------------- Consumer warps ----------------
    const int k0 = warpK * 8;
    const int q  = lane >> 3;        // matrix index 0..3 within ldmatrix.x4
    const int r  = lane & 7;         // row within matrix

    uint32_t offA[2], offB[2];
#pragma unroll
    for (int mi = 0; mi < 2; mi++) {
        const int row = warpM * 32 + mi * 16 + (q & 1) * 8 + r;
        const int col = k0 + (q >> 1) * 4;
        offA[mi] = sw(row, col);
    }
#pragma unroll
    for (int p = 0; p < 2; p++) {
        const int row = warpN * 32 + (2 * p + (q >> 1)) * 8 + r;
        const int col = k0 + (q & 1) * 4;
        offB[p] = sw(row, col);
    }

    float* Red = (float*)((char*)S + (dynBase - smem_u32(S))) + NS * (STAGE_BYTES / 4);
    const int grp   = warpM * 2 + warpN;
    const int rbase = (grp * 32 + lane) * 36;

    uint32_t af[2][2][4], bf[2][4][2];

    auto ld_frags = [&](uint32_t stageA, uint32_t stageB, int ch, int sel, bool roundX) {
        const uint32_t At = stageA + ch * CHUNK_BYTES;
        const uint32_t Bt = stageB + ch * CHUNK_BYTES;
        LDSM_X4(af[sel][0][0], af[sel][0][1], af[sel][0][2], af[sel][0][3], At + offA[0]);
        LDSM_X4(af[sel][1][0], af[sel][1][1], af[sel][1][2], af[sel][1][3], At + offA[1]);
        LDSM_X4(bf[sel][0][0], bf[sel][0][1], bf[sel][1][0], bf[sel][1][1], Bt + offB[0]);
        LDSM_X4(bf[sel][2][0], bf[sel][2][1], bf[sel][3][0], bf[sel][3][1], Bt + offB[1]);
        if (roundX) {   // raw X fragments: apply rna tf32 rounding in-register
#pragma unroll
            for (int mi = 0; mi < 2; mi++)
#pragma unroll
                for (int v = 0; v < 4; v++)
                    af[sel][mi][v] = tf32r_u(af[sel][mi][v]);
        }
    };

    int s = 0;
    for (int t = 0; t < SEQ; t++) {
        float acc[2][4][4];
#pragma unroll
        for (int mi = 0; mi < 2; mi++)
#pragma unroll
            for (int ni = 0; ni < 4; ni++)
#pragma unroll
                for (int rr = 0; rr < 4; rr++) acc[mi][ni][rr] = 0.0f;

        for (int kt = 0; kt < NKT; kt++, s++) {
            const int slot = s % NS;
            const int j    = s / NS;
            const bool isX = (kt < NXS);
            MBARRIER_WAIT_PARITY(smem_u32(&mb_full[slot]), j & 1);

            const uint32_t stageA = dynBase + slot * STAGE_BYTES;
            const uint32_t stageB = stageA + A_BYTES;

            ld_frags(stageA, stageB, 0, 0, isX);
#pragma unroll
            for (int ch = 0; ch < NCH; ch++) {
                const int sel = ch & 1;
                if (ch + 1 < NCH) {
                    ld_frags(stageA, stageB, ch + 1, sel ^ 1, isX);
                    if (ch + 2 == NCH && lane == 0)   // last LDSM of stage done
                        MBARRIER_ARRIVE(smem_u32(&mb_empty[slot]));
                }
#pragma unroll
                for (int mi = 0; mi < 2; mi++)
#pragma unroll
                    for (int ni = 0; ni < 4; ni++)
                        MMA_TF32(acc[mi][ni], af[sel][mi], bf[sel][ni]);
            }
        }

        // ---- Sequential warpK reduction in dedicated scratch ----
        auto st_acc = [&]() {
#pragma unroll
            for (int mi = 0; mi < 2; mi++)
#pragma unroll
                for (int ni = 0; ni < 4; ni++)
                    *(float4*)&Red[rbase + mi * 16 + ni * 4] =
                        make_float4(acc[mi][ni][0], acc[mi][ni][1],
                                    acc[mi][ni][2], acc[mi][ni][3]);
        };
        auto add_acc = [&]() {
#pragma unroll
            for (int mi = 0; mi < 2; mi++)
#pragma unroll
                for (int ni = 0; ni < 4; ni++) {
                    float4 v = *(float4*)&Red[rbase + mi * 16 + ni * 4];
                    acc[mi][ni][0] += v.x; acc[mi][ni][1] += v.y;
                    acc[mi][ni][2] += v.z; acc[mi][ni][3] += v.w;
                }
        };
        if (warpK == 1) st_acc();
        BAR_CONS();
        if (warpK == 0) add_acc();
        BAR_CONS();
        if (warpK == 3) st_acc();
        BAR_CONS();
        if (warpK == 2) add_acc();
        BAR_CONS();
        if (warpK == 2) st_acc();
        BAR_CONS();

        if (warpK == 0) {
            add_acc();
            // ---- Epilogue: bias + sigmoid (t<SEQ-1) + tf32 rounding ----
            float* __restrict__ Hout = g_H[(t + 1) & 1];
            const bool sig = (t < SEQ - 1);
            const int rBase = mBase + warpM * 32;
            const int cBase = nBase + warpN * 32;
#pragma unroll
            for (int mi = 0; mi < 2; mi++) {
#pragma unroll
                for (int ni = 0; ni < 4; ni++) {
                    const int c  = cBase + ni * 8 + 2 * tig;
                    const float b0 = bias[c];
                    const float b1 = bias[c + 1];
                    const int r0 = rBase + mi * 16 + g;
                    float z0 = acc[mi][ni][0] + b0;
                    float z1 = acc[mi][ni][1] + b1;
                    float z2 = acc[mi][ni][2] + b0;
                    float z3 = acc[mi][ni][3] + b1;
                    if (sig) {
                        z0 = tf32r(1.0f / (1.0f + __expf(-z0)));
                        z1 = tf32r(1.0f / (1.0f + __expf(-z1)));
                        z2 = tf32r(1.0f / (1.0f + __expf(-z2)));
                        z3 = tf32r(1.0f / (1.0f + __expf(-z3)));
                    }
                    *(float2*)&Hout[(size_t)r0 * HD + c]       = make_float2(z0, z1);
                    *(float2*)&Hout[(size_t)(r0 + 8) * HD + c] = make_float2(z2, z3);
                }
            }
            __threadfence();   // publish H writes before the release flag
        }
        BAR_CONS();
        if (tid == 0) strel(&g_step[gy * 16 + blockIdx.x], (unsigned)(t + 1));
    }
}

// ---------------------------------------------------------------------------
// Final: out[b] = H_final[b] . W_hy  (fp32, one warp per row)
// ---------------------------------------------------------------------------
__global__ void out_kernel(const float* __restrict__ Why, float* __restrict__ out) {
    const int warp = threadIdx.x >> 5;
    const int lane = threadIdx.x & 31;
    const int row  = blockIdx.x * 4 + warp;
    const float* h = g_H[0] + (size_t)row * HD;   // after 256 steps -> buffer 0
    float s = 0.0f;
    for (int n = lane; n < HD; n += 32) s += h[n] * Why[n];
#pragma unroll
    for (int o = 16; o; o >>= 1) s += __shfl_xor_sync(0xFFFFFFFFu, s, o);
    if (lane == 0) out[row] = s;
}

// ---------------------------------------------------------------------------
// Host: tensormap construction via driver entry point (no -lcuda link dep)
// ---------------------------------------------------------------------------
typedef CUresult (*EncodeTiledFn)(
    CUtensorMap*, CUtensorMapDataType, unsigned int, void*,
    const unsigned long long*, const unsigned long long*,
    const unsigned int*, const unsigned int*,
    CUtensorMapInterleave, CUtensorMapSwizzle,
    CUtensorMapL2promotion, CUtensorMapFloatOOBfill);

static void encode3d(EncodeTiledFn fn, CUtensorMap* tm, void* ptr,
                     unsigned long long d0, unsigned long long d1, unsigned long long d2,
                     unsigned long long s1B, unsigned long long s2B,
                     unsigned int b0, unsigned int b1, unsigned int b2) {
    unsigned long long dims[3]    = {d0, d1, d2};
    unsigned long long strides[2] = {s1B, s2B};
    unsigned int box[3]           = {b0, b1, b2};
    unsigned int es[3]            = {1, 1, 1};
    fn(tm, CU_TENSOR_MAP_DATA_TYPE_FLOAT32, 3, ptr, dims, strides, box, es,
       CU_TENSOR_MAP_INTERLEAVE_NONE, CU_TENSOR_MAP_SWIZZLE_128B,
       CU_TENSOR_MAP_L2_PROMOTION_L2_128B, CU_TENSOR_MAP_FLOAT_OOB_FILL_NONE);
}

extern "C" void kernel_launch(void* const* d_in, const int* in_sizes, int n_in,
                              void* d_out, int out_size) {
    const float* X    = (const float*)d_in[0];   // [512, 256, 512]
    const float* Whh  = (const float*)d_in[1];   // [1024, 1024]
    const float* Wxh  = (const float*)d_in[2];   // [1024, 512]
    const float* Why  = (const float*)d_in[3];   // [1024]
    const float* bias = (const float*)d_in[4];   // [1024]
    float* out = (float*)d_out;                  // [512]

    EncodeTiledFn encode = nullptr;
    {
        void* p = nullptr;
        cudaDriverEntryPointQueryResult qr;
        cudaGetDriverEntryPoint("cuTensorMapEncodeTiled", &p, cudaEnableDefault, &qr);
        encode = (EncodeTiledFn)p;
    }

    void *pW = nullptr, *pH = nullptr;
    cudaGetSymbolAddress(&pW, g_W);
    cudaGetSymbolAddress(&pH, g_H);
    float* H0 = (float*)pH;
    float* H1 = H0 + (size_t)BATCH * HD;

    CUtensorMap tH0, tH1, tX, tW;
    // H[b][k]: dims (1024, 512), box (32, 64)
    encode3d(encode, &tH0, H0, HD, BATCH, 1, (unsigned long long)HD * 4,
             (unsigned long long)BATCH * HD * 4, 32, MT, 1);
    encode3d(encode, &tH1, H1, HD, BATCH, 1, (unsigned long long)HD * 4,
             (unsigned long long)BATCH * HD * 4, 32, MT, 1);
    // Raw X[b][t][k]: dims (512, 256, 512), box (32, 1, 64)
    encode3d(encode, &tX, (void*)X, XD, SEQ, BATCH, (unsigned long long)XD * 4,
             (unsigned long long)SEQ * XD * 4, 32, 1, MT);
    // W[n][k]: dims (1536, 1024), box (32, 64)
    encode3d(encode, &tW, pW, KTOT, HD, 1, (unsigned long long)KTOT * 4,
             (unsigned long long)HD * KTOT * 4, 32, NT, 1);

    cudaFuncSetAttribute(rnn_kernel,
                         cudaFuncAttributeMaxDynamicSharedMemorySize, SMEM_BYTES);

    pack_w_kernel<<<(HD * KTOT + 255) / 256, 256>>>(Whh, Wxh);
    zero_kernel<<<BATCH, 1024>>>();

    dim3 grid(HD / NT, BATCH / MT);  // (16, 8) = 128 CTAs, all co-resident
    rnn_kernel<<<grid, THREADS, SMEM_BYTES>>>(tH0, tH1, tX, tW, bias);

    out_kernel<<<BATCH / 4, 128>>>(Why, out);
}

// round 17
// speedup vs baseline: 1.2202x; 1.2202x over previous
#include <cuda.h>
#include <cuda_runtime.h>
#include <cstdint>
#include <cstddef>

// Problem constants
#define BATCH 512
#define SEQ   256
#define XD    512
#define HD    1024
#define KTOT  (HD + XD)   // 1536

// GEMM tiling
#define MT   64
#define NT   64
#define KT   128           // k per stage = 4 chunks of 32 (SW128 128B rows)
#define NCH  4
#define NKT  (KTOT / KT)   // 12 stages per step (0..3 = X, 4..11 = H)
#define NXS  4             // X stages per step
#define THREADS 544        // 16 consumer warps + 1 producer warp
#define NS   3             // mbarrier ring stages
#define CHUNK_BYTES 8192                    // 64 rows x 128B
#define A_BYTES (NCH * CHUNK_BYTES)         // 32768
#define B_BYTES (NCH * CHUNK_BYTES)         // 32768
#define STAGE_BYTES (A_BYTES + B_BYTES)     // 65536
#define SLOT_BYTES (4 * 8 * 32 * 16)        // 16384: (grp, idx, lane) float4s
#define SMEM_BYTES (NS * STAGE_BYTES + 2 * SLOT_BYTES + 1024)  // 230400

// Static device scratch (allocation-free rule)
__device__ float    g_W[HD * KTOT];           // prepacked tf32-rounded [W_hh | W_xh]
__device__ float    g_H[2][BATCH * HD];       // ping-pong hidden state
__device__ unsigned g_ctr[8];                 // per-y step-completion counters

__device__ __forceinline__ float tf32r(float x) {
    uint32_t u;
    asm("cvt.rna.tf32.f32 %0, %1;" : "=r"(u) : "f"(x));
    return __uint_as_float(u);
}

__device__ __forceinline__ uint32_t tf32r_u(uint32_t x) {
    uint32_t u;
    asm("cvt.rna.tf32.f32 %0, %1;" : "=r"(u) : "f"(__uint_as_float(x)));
    return u;
}

__device__ __forceinline__ uint32_t smem_u32(const void* p) {
    return (uint32_t)__cvta_generic_to_shared(p);
}

#define MMA_TF32(c, a, b)                                                   \
    asm volatile(                                                           \
        "mma.sync.aligned.m16n8k8.row.col.f32.tf32.tf32.f32 "               \
        "{%0,%1,%2,%3}, {%4,%5,%6,%7}, {%8,%9}, {%0,%1,%2,%3};\n"           \
        : "+f"((c)[0]), "+f"((c)[1]), "+f"((c)[2]), "+f"((c)[3])            \
        : "r"((a)[0]), "r"((a)[1]), "r"((a)[2]), "r"((a)[3]),               \
          "r"((b)[0]), "r"((b)[1]))

#define LDSM_X4(r0, r1, r2, r3, addr)                                       \
    asm volatile("ldmatrix.sync.aligned.m8n8.x4.shared.b16 {%0,%1,%2,%3}, [%4];" \
        : "=r"(r0), "=r"(r1), "=r"(r2), "=r"(r3) : "r"(addr))

#define MBARRIER_INIT(a, c) \
    asm volatile("mbarrier.init.shared.b64 [%0], %1;" :: "r"(a), "r"((uint32_t)(c)) : "memory")
#define MBARRIER_ARRIVE(a) \
    asm volatile("mbarrier.arrive.shared.b64 _, [%0];" :: "r"(a) : "memory")
#define MBARRIER_EXPECT_TX(a, b) \
    asm volatile("mbarrier.arrive.expect_tx.shared.b64 _, [%0], %1;" :: "r"(a), "r"((uint32_t)(b)) : "memory")
#define FENCE_PROXY_ASYNC() \
    asm volatile("fence.proxy.async.shared::cta;" ::: "memory")
#define BAR_CONS() \
    asm volatile("bar.sync 1, 512;" ::: "memory")   // consumers only (512 threads)

#define MBARRIER_WAIT_PARITY(mbar_addr, phase) do {                              \
    uint32_t _m = (mbar_addr), _p = (phase), _d;                                 \
    asm volatile("{\n\t.reg .pred p;\n\t"                                        \
        "mbarrier.try_wait.parity.acquire.cta.shared::cta.b64 p, [%1], %2;\n\t"  \
        "selp.b32 %0, 1, 0, p;\n\t}" : "=r"(_d) : "r"(_m), "r"(_p) : "memory");  \
    if (!_d) {                                                                   \
        asm volatile("{\n\t.reg .pred P1;\n\t"                                   \
            "WL_%=:\n\t"                                                         \
            "mbarrier.try_wait.parity.acquire.cta.shared::cta.b64 P1, [%0], %1, 0x989680;\n\t" \
            "@P1 bra.uni WD_%=;\n\t"                                             \
            "bra.uni WL_%=;\n\t"                                                 \
            "WD_%=:\n\t}" :: "r"(_m), "r"(_p) : "memory");                       \
    }                                                                            \
} while (0)

#define TMA_LOAD_3D(smem_addr, map_ptr, cx, cy, cz, mbar) \
    asm volatile("cp.async.bulk.tensor.3d.shared::cta.global.tile.mbarrier::complete_tx::bytes " \
                 "[%0], [%1, {%2, %3, %4}], [%5];" \
                 :: "r"((uint32_t)(smem_addr)), "l"(map_ptr), \
                    "r"((int)(cx)), "r"((int)(cy)), "r"((int)(cz)), \
                    "r"((uint32_t)(mbar)) : "memory")

// SW128 swizzle: byte offset within a 64x128B tile
__device__ __forceinline__ uint32_t sw(int r, int c) {
    return (uint32_t)(r * 128 + ((c * 4) ^ ((r & 7) * 16)));
}

// ---------------------------------------------------------------------------
// Prep kernels
// ---------------------------------------------------------------------------
__global__ void pack_w_kernel(const float* __restrict__ Whh,
                              const float* __restrict__ Wxh) {
    int idx = blockIdx.x * 256 + threadIdx.x;
    if (idx >= HD * KTOT) return;
    int n = idx / KTOT;
    int k = idx - n * KTOT;
    float v = (k < HD) ? Whh[n * HD + k] : Wxh[n * XD + (k - HD)];
    g_W[idx] = tf32r(v);
}

__global__ void zero_kernel() {
    g_H[0][blockIdx.x * 1024 + threadIdx.x] = 0.0f;
    if (blockIdx.x == 0 && threadIdx.x < 8) g_ctr[threadIdx.x] = 0u;
}

// ---------------------------------------------------------------------------
// PERSISTENT RNN kernel: all 256 steps in one launch.
// Grid (16, 8) = 128 CTAs (all co-resident). 17 warps:
//   warps 0..15 consumers: (warpM 2) x (warpN 2) x (warpK 4), warp tile 32x32
//   warp 16: free-running TMA producer over 256*12 stages
// Stage order per step: X stages (0..3, ungated; raw X rounded in-register)
// then H stages (4..11) gated ONCE per step on the per-y counter (R14 gate —
// the per-stage fine gating of R15 put 16 L2 polls on the producer's serial
// path and regressed). Reduction: 2-slot coalesced scratch, 3 bar.syncs.
// ---------------------------------------------------------------------------
__global__ __launch_bounds__(THREADS, 1)
void rnn_kernel(const __grid_constant__ CUtensorMap tH0,
                const __grid_constant__ CUtensorMap tH1,
                const __grid_constant__ CUtensorMap tX,
                const __grid_constant__ CUtensorMap tB_W,
                const float* __restrict__ bias) {
    extern __shared__ __align__(16) float S[];
    __shared__ __align__(8) uint64_t mb_full[NS], mb_empty[NS];

    const int tid   = threadIdx.x;
    const int mBase = blockIdx.y * MT;
    const int nBase = blockIdx.x * NT;
    const int gy    = blockIdx.y;
    const int lane  = tid & 31;
    const int warp  = tid >> 5;          // 0..16
    const int warpK = (warp >> 2) & 3;   // consumers: 0..3
    const int warpM = (warp >> 1) & 1;
    const int warpN = warp & 1;
    const int g     = lane >> 2;         // 0..7
    const int tig   = lane & 3;          // 0..3

    const uint32_t dynBase = (smem_u32(S) + 1023u) & ~1023u;

    if (tid == 0) {
        for (int s = 0; s < NS; s++) {
            MBARRIER_INIT(smem_u32(&mb_full[s]), 1);    // expect_tx producer
            MBARRIER_INIT(smem_u32(&mb_empty[s]), 16);  // one per consumer warp
        }
        FENCE_PROXY_ASYNC();
    }
    __syncthreads();

    if (warp == 16) {
        // ---------------- Producer warp (single thread) ----------------
        if (lane == 0) {
            int s = 0;
            for (int t = 0; t < SEQ; t++) {
                for (int kt = 0; kt < NKT; kt++, s++) {
                    const int slot = s % NS;
                    const int j    = s / NS;
                    if (s >= NS)
                        MBARRIER_WAIT_PARITY(smem_u32(&mb_empty[slot]), (j - 1) & 1);
                    if (kt == NXS) {
                        // first H stage of step t: all 16 y-peers must have
                        // completed t steps (single L2 poll per step)
                        while (atomicAdd(&g_ctr[gy], 0u) < 16u * (unsigned)t) {}
                    }
                    const uint32_t aAddr = dynBase + slot * STAGE_BYTES;
                    const uint32_t bAddr = aAddr + A_BYTES;
                    const uint32_t fb = smem_u32(&mb_full[slot]);
                    MBARRIER_EXPECT_TX(fb, STAGE_BYTES);
                    if (kt < NXS) {
                        const int xk = kt * KT;
#pragma unroll
                        for (int ch = 0; ch < NCH; ch++) {
                            TMA_LOAD_3D(aAddr + ch * CHUNK_BYTES, &tX,
                                        xk + ch * 32, t, mBase, fb);
                            TMA_LOAD_3D(bAddr + ch * CHUNK_BYTES, &tB_W,
                                        HD + xk + ch * 32, nBase, 0, fb);
                        }
                    } else {
                        const int hk = (kt - NXS) * KT;
                        const CUtensorMap* th = (t & 1) ? &tH1 : &tH0;
#pragma unroll
                        for (int ch = 0; ch < NCH; ch++) {
                            TMA_LOAD_3D(aAddr + ch * CHUNK_BYTES, th,
                                        hk + ch * 32, mBase, 0, fb);
                            TMA_LOAD_3D(bAddr + ch * CHUNK_BYTES, &tB_W,
                                        hk + ch * 32, nBase, 0, fb);
                        }
                    }
                }
            }
        }
        return;   // producer never touches CTA-wide barriers again
    }

    // ---------------- Consumer warps ----------------
    const int k0 = warpK * 8;
    const int q  = lane >> 3;        // matrix index 0..3 within ldmatrix.x4
    const int r  = lane & 7;         // row within matrix

    uint32_t offA[2], offB[2];
#pragma unroll
    for (int mi = 0; mi < 2; mi++) {
        const int row = warpM * 32 + mi * 16 + (q & 1) * 8 + r;
        const int col = k0 + (q >> 1) * 4;
        offA[mi] = sw(row, col);
    }
#pragma unroll
    for (int p = 0; p < 2; p++) {
        const int row = warpN * 32 + (2 * p + (q >> 1)) * 8 + r;
        const int col = k0 + (q & 1) * 4;
        offB[p] = sw(row, col);
    }

    // 2-slot reduction scratch: float4 at ((grp*8 + idx)*32 + lane)*16B, coalesced.
    float* RedBase = (float*)((char*)S + (dynBase - smem_u32(S))) + NS * (STAGE_BYTES / 4);
    const int grp = warpM * 2 + warpN;
    float* slotA = RedBase + (grp * 8 * 32 + lane) * 4;
    float* slotB = slotA + (SLOT_BYTES / 4);

    uint32_t af[2][2][4], bf[2][4][2];

    auto ld_frags = [&](uint32_t stageA, uint32_t stageB, int ch, int sel, bool roundX) {
        const uint32_t At = stageA + ch * CHUNK_BYTES;
        const uint32_t Bt = stageB + ch * CHUNK_BYTES;
        LDSM_X4(af[sel][0][0], af[sel][0][1], af[sel][0][2], af[sel][0][3], At + offA[0]);
        LDSM_X4(af[sel][1][0], af[sel][1][1], af[sel][1][2], af[sel][1][3], At + offA[1]);
        LDSM_X4(bf[sel][0][0], bf[sel][0][1], bf[sel][1][0], bf[sel][1][1], Bt + offB[0]);
        LDSM_X4(bf[sel][2][0], bf[sel][2][1], bf[sel][3][0], bf[sel][3][1], Bt + offB[1]);
        if (roundX) {   // raw X fragments: apply rna tf32 rounding in-register
#pragma unroll
            for (int mi = 0; mi < 2; mi++)
#pragma unroll
                for (int v = 0; v < 4; v++)
                    af[sel][mi][v] = tf32r_u(af[sel][mi][v]);
        }
    };

    int s = 0;
    for (int t = 0; t < SEQ; t++) {
        float acc[2][4][4];
#pragma unroll
        for (int mi = 0; mi < 2; mi++)
#pragma unroll
            for (int ni = 0; ni < 4; ni++)
#pragma unroll
                for (int rr = 0; rr < 4; rr++) acc[mi][ni][rr] = 0.0f;

        for (int kt = 0; kt < NKT; kt++, s++) {
            const int slot = s % NS;
            const int j    = s / NS;
            const bool isX = (kt < NXS);
            MBARRIER_WAIT_PARITY(smem_u32(&mb_full[slot]), j & 1);

            const uint32_t stageA = dynBase + slot * STAGE_BYTES;
            const uint32_t stageB = stageA + A_BYTES;

            ld_frags(stageA, stageB, 0, 0, isX);
#pragma unroll
            for (int ch = 0; ch < NCH; ch++) {
                const int sel = ch & 1;
                if (ch + 1 < NCH) {
                    ld_frags(stageA, stageB, ch + 1, sel ^ 1, isX);
                    if (ch + 2 == NCH && lane == 0)   // last LDSM of stage done
                        MBARRIER_ARRIVE(smem_u32(&mb_empty[slot]));
                }
#pragma unroll
                for (int mi = 0; mi < 2; mi++)
#pragma unroll
                    for (int ni = 0; ni < 4; ni++)
                        MMA_TF32(acc[mi][ni], af[sel][mi], bf[sel][ni]);
            }
        }

        // ---- warpK reduction: 2-slot scratch, 3 consumer barriers ----
        auto st_to = [&](float* slot) {
#pragma unroll
            for (int mi = 0; mi < 2; mi++)
#pragma unroll
                for (int ni = 0; ni < 4; ni++)
                    *(float4*)(slot + (mi * 4 + ni) * 32 * 4) =
                        make_float4(acc[mi][ni][0], acc[mi][ni][1],
                                    acc[mi][ni][2], acc[mi][ni][3]);
        };
        auto add_from = [&](const float* slot) {
#pragma unroll
            for (int mi = 0; mi < 2; mi++)
#pragma unroll
                for (int ni = 0; ni < 4; ni++) {
                    float4 v = *(const float4*)(slot + (mi * 4 + ni) * 32 * 4);
                    acc[mi][ni][0] += v.x; acc[mi][ni][1] += v.y;
                    acc[mi][ni][2] += v.z; acc[mi][ni][3] += v.w;
                }
        };
        if (warpK == 1) st_to(slotA);
        if (warpK == 3) st_to(slotB);
        BAR_CONS();
        if (warpK == 0) add_from(slotA);
        if (warpK == 2) { add_from(slotB); st_to(slotA); }
        BAR_CONS();

        if (warpK == 0) {
            add_from(slotA);
            // ---- Epilogue: bias + sigmoid (t<SEQ-1) + tf32 rounding ----
            float* __restrict__ Hout = g_H[(t + 1) & 1];
            const bool sig = (t < SEQ - 1);
            const int rBase = mBase + warpM * 32;
            const int cBase = nBase + warpN * 32;
#pragma unroll
            for (int mi = 0; mi < 2; mi++) {
#pragma unroll
                for (int ni = 0; ni < 4; ni++) {
                    const int c  = cBase + ni * 8 + 2 * tig;
                    const float b0 = bias[c];
                    const float b1 = bias[c + 1];
                    const int r0 = rBase + mi * 16 + g;
                    float z0 = acc[mi][ni][0] + b0;
                    float z1 = acc[mi][ni][1] + b1;
                    float z2 = acc[mi][ni][2] + b0;
                    float z3 = acc[mi][ni][3] + b1;
                    if (sig) {
                        z0 = tf32r(1.0f / (1.0f + __expf(-z0)));
                        z1 = tf32r(1.0f / (1.0f + __expf(-z1)));
                        z2 = tf32r(1.0f / (1.0f + __expf(-z2)));
                        z3 = tf32r(1.0f / (1.0f + __expf(-z3)));
                    }
                    *(float2*)&Hout[(size_t)r0 * HD + c]       = make_float2(z0, z1);
                    *(float2*)&Hout[(size_t)(r0 + 8) * HD + c] = make_float2(z2, z3);
                }
            }
            __threadfence();   // publish H writes before the release count
        }
        BAR_CONS();
        if (tid == 0) atomicAdd(&g_ctr[gy], 1u);   // release step t for y-peers
    }
}

// ---------------------------------------------------------------------------
// Final: out[b] = H_final[b] . W_hy  (fp32, one warp per row)
// ---------------------------------------------------------------------------
__global__ void out_kernel(const float* __restrict__ Why, float* __restrict__ out) {
    const int warp = threadIdx.x >> 5;
    const int lane = threadIdx.x & 31;
    const int row  = blockIdx.x * 4 + warp;
    const float* h = g_H[0] + (size_t)row * HD;   // after 256 steps -> buffer 0
    float s = 0.0f;
    for (int n = lane; n < HD; n += 32) s += h[n] * Why[n];
#pragma unroll
    for (int o = 16; o; o >>= 1) s += __shfl_xor_sync(0xFFFFFFFFu, s, o);
    if (lane == 0) out[row] = s;
}

// ---------------------------------------------------------------------------
// Host: tensormap construction via driver entry point (no -lcuda link dep)
// ---------------------------------------------------------------------------
typedef CUresult (*EncodeTiledFn)(
    CUtensorMap*, CUtensorMapDataType, unsigned int, void*,
    const unsigned long long*, const unsigned long long*,
    const unsigned int*, const unsigned int*,
    CUtensorMapInterleave, CUtensorMapSwizzle,
    CUtensorMapL2promotion, CUtensorMapFloatOOBfill);

static void encode3d(EncodeTiledFn fn, CUtensorMap* tm, void* ptr,
                     unsigned long long d0, unsigned long long d1, unsigned long long d2,
                     unsigned long long s1B, unsigned long long s2B,
                     unsigned int b0, unsigned int b1, unsigned int b2) {
    unsigned long long dims[3]    = {d0, d1, d2};
    unsigned long long strides[2] = {s1B, s2B};
    unsigned int box[3]           = {b0, b1, b2};
    unsigned int es[3]            = {1, 1, 1};
    fn(tm, CU_TENSOR_MAP_DATA_TYPE_FLOAT32, 3, ptr, dims, strides, box, es,
       CU_TENSOR_MAP_INTERLEAVE_NONE, CU_TENSOR_MAP_SWIZZLE_128B,
       CU_TENSOR_MAP_L2_PROMOTION_L2_128B, CU_TENSOR_MAP_FLOAT_OOB_FILL_NONE);
}

extern "C" void kernel_launch(void* const* d_in, const int* in_sizes, int n_in,
                              void* d_out, int out_size) {
    const float* X    = (const float*)d_in[0];   // [512, 256, 512]
    const float* Whh  = (const float*)d_in[1];   // [1024, 1024]
    const float* Wxh  = (const float*)d_in[2];   // [1024, 512]
    const float* Why  = (const float*)d_in[3];   // [1024]
    const float* bias = (const float*)d_in[4];   // [1024]
    float* out = (float*)d_out;                  // [512]

    EncodeTiledFn encode = nullptr;
    {
        void* p = nullptr;
        cudaDriverEntryPointQueryResult qr;
        cudaGetDriverEntryPoint("cuTensorMapEncodeTiled", &p, cudaEnableDefault, &qr);
        encode = (EncodeTiledFn)p;
    }

    void *pW = nullptr, *pH = nullptr;
    cudaGetSymbolAddress(&pW, g_W);
    cudaGetSymbolAddress(&pH, g_H);
    float* H0 = (float*)pH;
    float* H1 = H0 + (size_t)BATCH * HD;

    CUtensorMap tH0, tH1, tX, tW;
    // H[b][k]: dims (1024, 512), box (32, 64)
    encode3d(encode, &tH0, H0, HD, BATCH, 1, (unsigned long long)HD * 4,
             (unsigned long long)BATCH * HD * 4, 32, MT, 1);
    encode3d(encode, &tH1, H1, HD, BATCH, 1, (unsigned long long)HD * 4,
             (unsigned long long)BATCH * HD * 4, 32, MT, 1);
    // Raw X[b][t][k]: dims (512, 256, 512), box (32, 1, 64)
    encode3d(encode, &tX, (void*)X, XD, SEQ, BATCH, (unsigned long long)XD * 4,
             (unsigned long long)SEQ * XD * 4, 32, 1, MT);
    // W[n][k]: dims (1536, 1024), box (32, 64)
    encode3d(encode, &tW, pW, KTOT, HD, 1, (unsigned long long)KTOT * 4,
             (unsigned long long)HD * KTOT * 4, 32, NT, 1);

    cudaFuncSetAttribute(rnn_kernel,
                         cudaFuncAttributeMaxDynamicSharedMemorySize, SMEM_BYTES);

    pack_w_kernel<<<(HD * KTOT + 255) / 256, 256>>>(Whh, Wxh);
    zero_kernel<<<BATCH, 1024>>>();

    dim3 grid(HD / NT, BATCH / MT);  // (16, 8) = 128 CTAs, all co-resident
    rnn_kernel<<<grid, THREADS, SMEM_BYTES>>>(tH0, tH1, tX, tW, bias);

    out_kernel<<<BATCH / 4, 128>>>(Why, out);
}